// round 9
// baseline (speedup 1.0000x reference)
#include <cuda_runtime.h>
#include <math.h>

#define Bn    128
#define Tn    128
#define In    512
#define Hn    512
#define Dn    1024
#define Nn    513
#define NP    576
#define DEPTH 4
#define EPSV  1e-5f
#define NCTA  148
#define NTHR  256
#define TEAMS 16
#define TCTA  9
#define TB    8

typedef unsigned long long u64t;

// ----------------------------- device state --------------------------------
__device__ float g_Wp[Dn * NP];
__device__ float g_Up[Dn * NP];
__device__ float g_X[Tn * Bn * Dn];          // xs / h_seq in place
__device__ float g_XWraw[Tn * Bn * NP];
__device__ float g_spre[Tn * Bn * NP];
__device__ float g_h[Bn * Dn];
__device__ float g_xch[TEAMS * TCTA * TB * 2]; // (sum,sumsq) per strip/batch
__device__ float g_g0[TEAMS * TB];             // raw G col0 per batch
__device__ float g_seqF[2][Tn * Bn];           // fk_seq double buffer
__device__ float g_seqH[2][Tn * Bn];           // hv_seq double buffer
__device__ unsigned g_barCnt[24];              // 0..15 teams, 16 global
__device__ unsigned g_barEp[24];

// --------------------------- f32x2 packed math ------------------------------
__device__ __forceinline__ void ffma2(u64t& d, u64t a, u64t b) {
    asm("fma.rn.f32x2 %0, %1, %2, %0;" : "+l"(d) : "l"(a), "l"(b));
}
__device__ __forceinline__ u64t add2(u64t a, u64t b) {
    u64t d; asm("add.rn.f32x2 %0, %1, %2;" : "=l"(d) : "l"(a), "l"(b)); return d;
}
__device__ __forceinline__ u64t packdup(float x) {
    u64t r; asm("mov.b64 %0, {%1, %1};" : "=l"(r) : "f"(x)); return r;
}
__device__ __forceinline__ float2 unpack2(u64t v) {
    float2 f; asm("mov.b64 {%0, %1}, %2;" : "=f"(f.x), "=f"(f.y) : "l"(v)); return f;
}

// ------------------------------ barriers ------------------------------------
__device__ __forceinline__ unsigned ld_acq(unsigned* p) {
    unsigned v;
    asm volatile("ld.acquire.gpu.u32 %0, [%1];" : "=r"(v) : "l"(p) : "memory");
    return v;
}
__device__ __forceinline__ void barrier_sync(int idx, int n, unsigned& ep) {
    __syncthreads();
    if (threadIdx.x == 0) {
        ep += 1;
        __threadfence();
        unsigned prev = atomicAdd(&g_barCnt[idx], 1u);
        if (prev == (unsigned)(n - 1)) {
            atomicExch(&g_barCnt[idx], 0u);
            __threadfence();
            atomicExch(&g_barEp[idx], ep);
        } else {
            while (ld_acq(&g_barEp[idx]) < ep) { }
        }
        __threadfence();
    }
    __syncthreads();
}

// --------------------- 64x64 tile GEMM (xW phase, proven R7 code) -----------
__device__ __forceinline__ void tile_gemm64(
    const float* __restrict__ A, int lda,
    const float* __restrict__ Bm,
    float* __restrict__ C, int K, float* sh)
{
    float* hT = sh;            // [16][68]
    float* Us = sh + 16 * 68;  // [16][64]
    int tid  = threadIdx.x;
    int arow = tid >> 2, akq = (tid & 3) << 2;
    int brow = tid >> 4, bc  = (tid & 15) << 2;
    int ty   = tid >> 4, tx  = tid & 15;

    u64t acc2[4][2];
#pragma unroll
    for (int i = 0; i < 4; i++) { acc2[i][0] = 0ull; acc2[i][1] = 0ull; }

    const float* Aptr = A + arow * lda + akq;
    const float* Bptr = Bm + brow * NP + bc;
    float4 av = *(const float4*)Aptr;
    float4 bv = *(const float4*)Bptr;

    for (int k0 = 0; k0 < K; k0 += 16) {
        __syncthreads();
        hT[(akq + 0) * 68 + arow] = av.x;
        hT[(akq + 1) * 68 + arow] = av.y;
        hT[(akq + 2) * 68 + arow] = av.z;
        hT[(akq + 3) * 68 + arow] = av.w;
        *(float4*)(Us + (brow << 6) + bc) = bv;
        __syncthreads();
        if (k0 + 16 < K) {
            av = *(const float4*)(Aptr + k0 + 16);
            bv = *(const float4*)(Bptr + (size_t)(k0 + 16) * NP);
        }
#pragma unroll
        for (int kk = 0; kk < 16; kk++) {
            float4 a = *(float4*)(hT + kk * 68 + (ty << 2));
            const u64t* bp = (const u64t*)(Us + (kk << 6) + (tx << 2));
            u64t b0 = bp[0];
            u64t b1 = bp[1];
            u64t ad;
            ad = packdup(a.x); ffma2(acc2[0][0], ad, b0); ffma2(acc2[0][1], ad, b1);
            ad = packdup(a.y); ffma2(acc2[1][0], ad, b0); ffma2(acc2[1][1], ad, b1);
            ad = packdup(a.z); ffma2(acc2[2][0], ad, b0); ffma2(acc2[2][1], ad, b1);
            ad = packdup(a.w); ffma2(acc2[3][0], ad, b0); ffma2(acc2[3][1], ad, b1);
        }
    }
#pragma unroll
    for (int i = 0; i < 4; i++) {
        float2 lo = unpack2(acc2[i][0]);
        float2 hi = unpack2(acc2[i][1]);
        *(float4*)(C + (size_t)((ty << 2) + i) * NP + (tx << 2)) =
            make_float4(lo.x, lo.y, hi.x, hi.y);
    }
}

// ------------------------------ main kernel ---------------------------------
__global__ void __launch_bounds__(NTHR, 1) hrnn_kernel(
    const float* __restrict__ x, const int* __restrict__ mask,
    const float* __restrict__ W, const float* __restrict__ U,
    const float* __restrict__ bias, const float* __restrict__ gam,
    const float* __restrict__ bet, float* __restrict__ out)
{
    __shared__ __align__(16) float sh_buf[5120];  // xW tiles / scan Us+hdup
    __shared__ float sh_red[16];
    __shared__ float sh_sc[2];
    __shared__ float4 sm_go[TB];

    int cta = blockIdx.x, tid = threadIdx.x;
    int gtid = cta * NTHR + tid;
    const int nthr = NCTA * NTHR;

    // ------------------------------- prep -----------------------------------
    for (int i = gtid; i < Tn * Bn * Dn; i += nthr) {
        int d = i & (Dn - 1);
        int row = i >> 10;
        int t = row >> 7, b = row & 127;
        g_X[i] = (d < In) ? x[(b * Tn + t) * In + d] : 0.f;
    }
    for (int i = gtid; i < Dn * NP; i += nthr) {
        int col = i % NP, r = i / NP;
        float wv = 0.f, uv = 0.f;
        if (col < Nn) { wv = W[r * Nn + col]; uv = U[r * Nn + col]; }
        g_Wp[i] = wv;
        g_Up[i] = uv;
    }
    for (int i = gtid; i < Tn * Bn; i += nthr) {
        g_seqF[0][i] = 0.f;
        g_seqH[0][i] = 1.f;
    }

    unsigned epG = 0, epT = 0;
    int team = cta / TCTA;                 // valid for cta < 144
    int j    = cta - team * TCTA;
    bool in_team = (cta < TEAMS * TCTA);
    if (tid == 0) {
        epG = ld_acq(&g_barEp[16]);
        if (in_team) epT = ld_acq(&g_barEp[team]);
    }
    barrier_sync(16, NCTA, epG);

    const float* gam0 = gam;
    const float* gam1 = gam + Nn;
    const float* bet0 = bet;
    const float* bet1 = bet + Nn;

    // scan-static per-thread values
    int warp = tid >> 5, lane = tid & 31;
    int bb   = team * TB + warp;           // this warp's batch (scan)
    int c0   = j * 64 + (lane << 1);
    int c1   = c0 + 1;
    bool v0  = (c0 >= 1 && c0 <= 512);
    bool v1  = (c1 <= 512);
    int d0   = 511 + c0, d1 = 511 + c1;
    float gc0 = v0 ? gam1[c0] : 0.f, bc0v = v0 ? bet1[c0] : 0.f;
    float gc1 = v1 ? gam1[c1] : 0.f, bc1v = v1 ? bet1[c1] : 0.f;
    float gam1_0 = gam1[0], bet1_0 = bet1[0], bias0 = bias[0];
    // x-region assignment (dims 0..511 split across 9 strips)
    int dlo = j * 57;
    int cnt = (512 - dlo < 57) ? (512 - dlo) : 57;
    int tot = cnt * TB;
    int e1 = tid, e2 = tid + 256;
    bool a1 = e1 < tot, a2 = e2 < tot;
    int de1 = dlo + (e1 >> 3), be1 = team * TB + (e1 & 7);
    int de2 = dlo + (e2 >> 3), be2 = team * TB + (e2 & 7);

    float* us = sh_buf;                       // 64x64 floats
    u64t*  hs64 = (u64t*)&sh_buf[4096];       // 8x64 dup pairs

    for (int lev = 0; lev < DEPTH; lev++) {
        const float* seqF_rd = g_seqF[lev & 1];
        const float* seqH_rd = g_seqH[lev & 1];
        float* seqF_wr = g_seqF[1 - (lev & 1)];
        float* seqH_wr = g_seqH[1 - (lev & 1)];

        // -------- xW GEMM over all 2304 tiles + zero h (grid-wide) ----------
        for (int tau = cta; tau < Tn * 2 * TCTA; tau += NCTA) {
            int t = tau / 18, rem = tau % 18;
            int half = rem / TCTA, jj = rem % TCTA;
            tile_gemm64(&g_X[(size_t)(t * Bn + half * 64) * Dn], Dn,
                        &g_Wp[jj * 64],
                        &g_XWraw[(size_t)(t * Bn + half * 64) * NP + jj * 64],
                        Dn, sh_buf);
        }
        for (int i = gtid; i < Bn * Dn; i += nthr) g_h[i] = 0.f;
        barrier_sync(16, NCTA, epG);

        // -------- LN of xW rows -> spre (grid-wide) --------------------------
        for (int r = cta; r < Tn * Bn; r += NCTA) {
            const float* row = &g_XWraw[(size_t)r * NP];
            float v0r = row[tid];
            float v1r = row[tid + 256];
            float v2r = (tid == 0) ? row[512] : 0.f;
            float s = v0r + v1r + v2r;
            float q = v0r * v0r + v1r * v1r + v2r * v2r;
#pragma unroll
            for (int o = 16; o > 0; o >>= 1) {
                s += __shfl_down_sync(0xffffffffu, s, o);
                q += __shfl_down_sync(0xffffffffu, q, o);
            }
            if ((tid & 31) == 0) { sh_red[tid >> 5] = s; sh_red[8 + (tid >> 5)] = q; }
            __syncthreads();
            if (tid == 0) {
                float S = 0.f, Q = 0.f;
#pragma unroll
                for (int w = 0; w < 8; w++) { S += sh_red[w]; Q += sh_red[8 + w]; }
                float mean = S * (1.f / (float)Nn);
                float var  = Q * (1.f / (float)Nn) - mean * mean;
                sh_sc[0] = mean;
                sh_sc[1] = 1.f / (sqrtf(var + EPSV) + EPSV);
            }
            __syncthreads();
            float mean = sh_sc[0], inv = sh_sc[1];
            float* o = &g_spre[(size_t)r * NP];
            o[tid]       = gam0[tid] * ((v0r - mean) * inv) + bet0[tid] + bias[tid];
            o[tid + 256] = gam0[tid + 256] * ((v1r - mean) * inv) + bet0[tid + 256] + bias[tid + 256];
            if (tid == 0)
                o[512] = gam0[512] * ((v2r - mean) * inv) + bet0[512] + bias[512];
            __syncthreads();
        }
        barrier_sync(16, NCTA, epG);

        // --------------------------- team scan -------------------------------
        if (in_team) {
            float fk_c = 0.f, hv_c = 0.f;   // warp-local carries (all lanes)
            bool prevmk = false;

            for (int t = 0; t < Tn; t++) {
                size_t rowb = (size_t)(t * Bn + bb);
                // ---- prefetch update-phase operands (hidden under GEMM) ----
                float2 spre2 = *(const float2*)&g_spre[rowb * NP + c0];
                float sp0    = __ldcg(&g_spre[rowb * NP]);
                int   mval   = __ldg(&mask[bb * Tn + t]);
                float fkpt   = __ldcg(&seqF_rd[t * Bn + bb]);
                float fkpv   = (t + 1 < Tn) ? __ldcg(&seqF_rd[(t + 1) * Bn + bb]) : 0.f;
                float hvpv   = __ldcg(&seqH_rd[t * Bn + bb]);
                float hA0 = v0 ? __ldcg(&g_h[(size_t)bb * Dn + d0]) : 0.f;
                float hA1 = v1 ? __ldcg(&g_h[(size_t)bb * Dn + d1]) : 0.f;
                float xA0 = v0 ? g_X[rowb * Dn + d0] : 0.f;
                float xA1 = v1 ? g_X[rowb * Dn + d1] : 0.f;
                float hx1 = a1 ? __ldcg(&g_h[(size_t)be1 * Dn + de1]) : 0.f;
                float xx1 = a1 ? g_X[(size_t)(t * Bn + be1) * Dn + de1] : 0.f;
                float hx2 = a2 ? __ldcg(&g_h[(size_t)be2 * Dn + de2]) : 0.f;
                float xx2 = a2 ? g_X[(size_t)(t * Bn + be2) * Dn + de2] : 0.f;

                // ------------------- GEMM: G strip = h @ U ------------------
                u64t acc0 = 0, acc1 = 0, acc2v = 0, acc3 = 0;
                {
                    int skk = tid >> 4, sc4 = (tid & 15) << 2;
                    int hr0 = tid >> 6, hk = tid & 63;
                    int hr1 = hr0 + 4;
                    const float* ub = &g_Up[(size_t)skk * NP + j * 64 + sc4];
                    float4 pu0 = *(const float4*)(ub);
                    float4 pu1 = *(const float4*)(ub + (size_t)16 * NP);
                    float4 pu2 = *(const float4*)(ub + (size_t)32 * NP);
                    float4 pu3 = *(const float4*)(ub + (size_t)48 * NP);
                    float ph0 = __ldcg(&g_h[(size_t)(team * TB + hr0) * Dn + hk]);
                    float ph1 = __ldcg(&g_h[(size_t)(team * TB + hr1) * Dn + hk]);

                    for (int cc = 0; cc < 16; cc++) {
                        __syncthreads();
                        *(float4*)&us[(skk)      * 64 + sc4] = pu0;
                        *(float4*)&us[(skk + 16) * 64 + sc4] = pu1;
                        *(float4*)&us[(skk + 32) * 64 + sc4] = pu2;
                        *(float4*)&us[(skk + 48) * 64 + sc4] = pu3;
                        hs64[tid]       = packdup(ph0);
                        hs64[tid + 256] = packdup(ph1);
                        __syncthreads();
                        if (cc < 15) {
                            int k0n = (cc + 1) * 64;
                            const float* ubn = ub + (size_t)k0n * NP;
                            pu0 = *(const float4*)(ubn);
                            pu1 = *(const float4*)(ubn + (size_t)16 * NP);
                            pu2 = *(const float4*)(ubn + (size_t)32 * NP);
                            pu3 = *(const float4*)(ubn + (size_t)48 * NP);
                            ph0 = __ldcg(&g_h[(size_t)(team * TB + hr0) * Dn + k0n + hk]);
                            ph1 = __ldcg(&g_h[(size_t)(team * TB + hr1) * Dn + k0n + hk]);
                        }
                        const u64t* hrow = hs64 + (warp << 6);
                        const u64t* urow = (const u64t*)us;
#pragma unroll 16
                        for (int kk = 0; kk < 64; kk += 4) {
                            ffma2(acc0,  hrow[kk + 0], urow[(kk + 0) * 32 + lane]);
                            ffma2(acc1,  hrow[kk + 1], urow[(kk + 1) * 32 + lane]);
                            ffma2(acc2v, hrow[kk + 2], urow[(kk + 2) * 32 + lane]);
                            ffma2(acc3,  hrow[kk + 3], urow[(kk + 3) * 32 + lane]);
                        }
                    }
                }
                float2 r2 = unpack2(add2(add2(acc0, acc1), add2(acc2v, acc3)));

                // row (sum,sumsq) via warp reduce (warp == batch row)
                float Sv = r2.x + r2.y;
                float Qv = r2.x * r2.x + r2.y * r2.y;
#pragma unroll
                for (int o = 16; o > 0; o >>= 1) {
                    Sv += __shfl_down_sync(0xffffffffu, Sv, o);
                    Qv += __shfl_down_sync(0xffffffffu, Qv, o);
                }
                if (lane == 0) {
                    *(float2*)&g_xch[((team * TCTA + j) * TB + warp) * 2] =
                        make_float2(Sv, Qv);
                    if (j == 0) g_g0[team * TB + warp] = r2.x;   // raw col0
                }
                barrier_sync(team, TCTA, epT);

                // ---------------- gates (redundant per warp) ----------------
                float S = 0.f, Q = 0.f;
#pragma unroll
                for (int jj = 0; jj < TCTA; jj++) {
                    float2 p = __ldcg((const float2*)&g_xch[((team * TCTA + jj) * TB + warp) * 2]);
                    S += p.x; Q += p.y;
                }
                float G0 = __ldcg(&g_g0[team * TB + warp]);
                float mean = S * (1.f / (float)Nn);
                float var  = Q * (1.f / (float)Nn) - mean * mean;
                float inv  = 1.f / (sqrtf(var + EPSV) + EPSV);

                float sum2_0 = gam1_0 * ((G0 - mean) * inv) + bet1_0;
                float s0v = sp0 + sum2_0;
                bool mk  = mval > 0;
                bool mk2 = (t > 0) && prevmk && !mk;
                float fk_both = fminf(fmaxf(0.2f * s0v + 0.5f, 0.f), 1.f);
                float fk_t1   = fminf(fmaxf(0.2f * (sum2_0 + bias0) + 0.5f, 0.f), 1.f);
                float fk = fkpt + (1.f - fkpt) * (fk_c * fk_both + (1.f - fk_c) * fk_t1);
                if (mk2) fk = 0.f;

                float h_only = hv_c * fk * (fkpv + (1.f - fkpv) * (1.f - hvpv));
                float x_only = hvpv * (1.f - fkpv) * (1.f - fk + fk * (1.f - hv_c));
                float both   = (1.f - fkpv) * fk * hv_c * hvpv;
                float hv = 1.f - (1.f - h_only) * (1.f - x_only) * (1.f - both);

                float fk_out = mk ? fk : fk_c;
                float hv_out = mk ? hv : hv_c;
                if (mk2) fk_out = 0.f;
                float mkf = mk ? 1.f : 0.f;

                if (lane == 0) {
                    if (j == 0) {
                        seqF_wr[t * Bn + bb] = fk_out;
                        seqH_wr[t * Bn + bb] = hv_out;
                    }
                    sm_go[warp] = make_float4(h_only, x_only, mkf, 0.f);
                }
                fk_c = fk_out; hv_c = hv_out; prevmk = mk;

                // ------------- tanh-region h update (own strip) -------------
                if (v0) {
                    float sA = spre2.x + gc0 * ((r2.x - mean) * inv) + bc0v;
                    float hn = tanhf(sA);
                    float h = h_only * hA0 + x_only * xA0 + both * hn;
                    h = mkf * h + (1.f - mkf) * hA0;
                    g_h[(size_t)bb * Dn + d0] = h;
                    g_X[rowb * Dn + d0] = h;
                }
                if (v1) {
                    float sB = spre2.y + gc1 * ((r2.y - mean) * inv) + bc1v;
                    float hn = tanhf(sB);
                    float h = h_only * hA1 + x_only * xA1 + both * hn;
                    h = mkf * h + (1.f - mkf) * hA1;
                    g_h[(size_t)bb * Dn + d1] = h;
                    g_X[rowb * Dn + d1] = h;
                }
                __syncthreads();   // publish sm_go

                // --------------- x-region h update (dims < 512) -------------
                if (a1) {
                    float4 go = sm_go[e1 & 7];
                    float h = go.x * hx1 + go.y * xx1;
                    h = go.z * h + (1.f - go.z) * hx1;
                    g_h[(size_t)be1 * Dn + de1] = h;
                    g_X[(size_t)(t * Bn + be1) * Dn + de1] = h;
                }
                if (a2) {
                    float4 go = sm_go[e2 & 7];
                    float h = go.x * hx2 + go.y * xx2;
                    h = go.z * h + (1.f - go.z) * hx2;
                    g_h[(size_t)be2 * Dn + de2] = h;
                    g_X[(size_t)(t * Bn + be2) * Dn + de2] = h;
                }
                barrier_sync(team, TCTA, epT);
            }
        }
        barrier_sync(16, NCTA, epG);
    }

    // ------------------------------ output ----------------------------------
    for (int i = gtid; i < Bn * Hn; i += nthr) {
        int b = i >> 9, jj = i & 511;
        out[i] = g_h[(size_t)b * Dn + In + jj];
    }
}

// ------------------------------- launcher -----------------------------------
extern "C" void kernel_launch(void* const* d_in, const int* in_sizes, int n_in,
                              void* d_out, int out_size) {
    const float* x      = (const float*)d_in[0];
    const int*   mask   = (const int*)d_in[1];
    const float* W      = (const float*)d_in[2];
    const float* U      = (const float*)d_in[3];
    const float* bias   = (const float*)d_in[4];
    const float* gammas = (const float*)d_in[5];
    const float* betas  = (const float*)d_in[6];
    float* out = (float*)d_out;

    hrnn_kernel<<<NCTA, NTHR>>>(x, mask, W, U, bias, gammas, betas, out);
}

// round 10
// speedup vs baseline: 1.5210x; 1.5210x over previous
#include <cuda_runtime.h>
#include <math.h>

#define Bn    128
#define Tn    128
#define In    512
#define Hn    512
#define Dn    1024
#define Nn    513
#define NP    576
#define DEPTH 4
#define EPSV  1e-5f
#define NCTA  296          // 2 CTAs per SM
#define GCTA  148          // CTAs per group
#define GB    64           // batches per group
#define NTHR  256
#define KS    16           // split-K factor in scan

typedef unsigned long long u64t;

// ----------------------------- device state --------------------------------
__device__ float g_Wp[Dn * NP];
__device__ float g_Up[Dn * NP];
__device__ float g_X[Tn * Bn * Dn];        // xs / h_seq in place, row = t*Bn+b
__device__ float g_XWraw[Tn * Bn * NP];
__device__ float g_spre[Tn * Bn * NP];
__device__ float g_Gpart[2 * KS * GB * NP];  // [group*16+ks][64 rows][NP]
__device__ float g_h[Bn * Dn];
__device__ float g_fk[Bn];
__device__ float g_hv[Bn];
__device__ float g_fkseq[Tn * Bn];
__device__ float g_hvseq[Tn * Bn];
__device__ unsigned g_barCnt[4];           // 0,1: groups; 2: global
__device__ unsigned g_barEp[4];

// --------------------------- f32x2 packed math ------------------------------
__device__ __forceinline__ void ffma2(u64t& d, u64t a, u64t b) {
    asm("fma.rn.f32x2 %0, %1, %2, %0;" : "+l"(d) : "l"(a), "l"(b));
}
__device__ __forceinline__ u64t packdup(float x) {
    u64t r; asm("mov.b64 %0, {%1, %1};" : "=l"(r) : "f"(x)); return r;
}
__device__ __forceinline__ float2 unpack2(u64t v) {
    float2 f; asm("mov.b64 {%0, %1}, %2;" : "=f"(f.x), "=f"(f.y) : "l"(v)); return f;
}

// ------------------------------ barriers ------------------------------------
__device__ __forceinline__ unsigned ld_acq(unsigned* p) {
    unsigned v;
    asm volatile("ld.acquire.gpu.u32 %0, [%1];" : "=r"(v) : "l"(p) : "memory");
    return v;
}
__device__ __forceinline__ void barrier_sync(int idx, int n, unsigned& ep) {
    __syncthreads();
    if (threadIdx.x == 0) {
        ep += 1;
        __threadfence();
        unsigned prev = atomicAdd(&g_barCnt[idx], 1u);
        if (prev == (unsigned)(n - 1)) {
            atomicExch(&g_barCnt[idx], 0u);
            __threadfence();
            atomicExch(&g_barEp[idx], ep);
        } else {
            while (ld_acq(&g_barEp[idx]) < ep) { }
        }
        __threadfence();
    }
    __syncthreads();
}

// --------------------- 64x64 tile GEMM (C-strides = NP) ---------------------
// A: 64 rows, stride lda; B: K x 64 at Bm, stride NP; C: 64 x 64, stride NP.
// 256 threads, 4x4 microtile computed as 4x(2x f32x2), K multiple of 16.
__device__ __forceinline__ void tile_gemm64(
    const float* __restrict__ A, int lda,
    const float* __restrict__ Bm,
    float* __restrict__ C, int K, float* sh)
{
    float* hT = sh;            // [16][68]
    float* Us = sh + 16 * 68;  // [16][64]
    int tid  = threadIdx.x;
    int arow = tid >> 2, akq = (tid & 3) << 2;
    int brow = tid >> 4, bc  = (tid & 15) << 2;
    int ty   = tid >> 4, tx  = tid & 15;

    u64t acc2[4][2];
#pragma unroll
    for (int i = 0; i < 4; i++) { acc2[i][0] = 0ull; acc2[i][1] = 0ull; }

    const float* Aptr = A + arow * lda + akq;
    const float* Bptr = Bm + brow * NP + bc;
    float4 av = *(const float4*)Aptr;
    float4 bv = *(const float4*)Bptr;

    for (int k0 = 0; k0 < K; k0 += 16) {
        __syncthreads();
        hT[(akq + 0) * 68 + arow] = av.x;
        hT[(akq + 1) * 68 + arow] = av.y;
        hT[(akq + 2) * 68 + arow] = av.z;
        hT[(akq + 3) * 68 + arow] = av.w;
        *(float4*)(Us + (brow << 6) + bc) = bv;
        __syncthreads();
        if (k0 + 16 < K) {
            av = *(const float4*)(Aptr + k0 + 16);
            bv = *(const float4*)(Bptr + (size_t)(k0 + 16) * NP);
        }
#pragma unroll
        for (int kk = 0; kk < 16; kk++) {
            float4 a = *(float4*)(hT + kk * 68 + (ty << 2));
            const u64t* bp = (const u64t*)(Us + (kk << 6) + (tx << 2));
            u64t b0 = bp[0];
            u64t b1 = bp[1];
            u64t ad;
            ad = packdup(a.x); ffma2(acc2[0][0], ad, b0); ffma2(acc2[0][1], ad, b1);
            ad = packdup(a.y); ffma2(acc2[1][0], ad, b0); ffma2(acc2[1][1], ad, b1);
            ad = packdup(a.z); ffma2(acc2[2][0], ad, b0); ffma2(acc2[2][1], ad, b1);
            ad = packdup(a.w); ffma2(acc2[3][0], ad, b0); ffma2(acc2[3][1], ad, b1);
        }
    }
#pragma unroll
    for (int i = 0; i < 4; i++) {
        float2 lo = unpack2(acc2[i][0]);
        float2 hi = unpack2(acc2[i][1]);
        *(float4*)(C + (size_t)((ty << 2) + i) * NP + (tx << 2)) =
            make_float4(lo.x, lo.y, hi.x, hi.y);
    }
}

// ------------------------------ main kernel ---------------------------------
__global__ void __launch_bounds__(NTHR, 2) hrnn_kernel(
    const float* __restrict__ x, const int* __restrict__ mask,
    const float* __restrict__ W, const float* __restrict__ U,
    const float* __restrict__ bias, const float* __restrict__ gam,
    const float* __restrict__ bet, float* __restrict__ out)
{
    __shared__ __align__(16) float sh_gemm[16 * 68 + 16 * 64];
    __shared__ float sh_s[Nn];
    __shared__ float sh_red[16];
    __shared__ float sh_sc[8];

    int cta = blockIdx.x, tid = threadIdx.x;
    int gtid = cta * NTHR + tid;
    const int nthr = NCTA * NTHR;

    // ------------------------------- prep -----------------------------------
    for (int i = gtid; i < Tn * Bn * Dn; i += nthr) {
        int d = i & (Dn - 1);
        int row = i >> 10;
        int t = row >> 7, b = row & 127;
        g_X[i] = (d < In) ? x[(b * Tn + t) * In + d] : 0.f;
    }
    for (int i = gtid; i < Dn * NP; i += nthr) {
        int col = i % NP, r = i / NP;
        float wv = 0.f, uv = 0.f;
        if (col < Nn) { wv = W[r * Nn + col]; uv = U[r * Nn + col]; }
        g_Wp[i] = wv;
        g_Up[i] = uv;
    }
    for (int i = gtid; i < Tn * Bn; i += nthr) { g_fkseq[i] = 0.f; g_hvseq[i] = 1.f; }

    // group interleave: each SM hosts one CTA of each group
    int g = cta & 1;
    int c = cta >> 1;
    unsigned epG = 0, epL = 0;
    if (tid == 0) {
        epG = ld_acq(&g_barEp[2]);   // persistent-counter-safe base
        epL = ld_acq(&g_barEp[g]);
    }
    barrier_sync(2, NCTA, epG);

    const float* gam0 = gam;
    const float* gam1 = gam + Nn;
    const float* bet0 = bet;
    const float* bet1 = bet + Nn;
    const int b0g = g * GB;

    for (int lev = 0; lev < DEPTH; lev++) {
        // ---------------- xW GEMM: 128 t-tiles x 9 col strips ----------------
        for (int tau = c; tau < Tn * 9; tau += GCTA) {
            int t = tau / 9, j = tau - t * 9;
            tile_gemm64(&g_X[(size_t)(t * Bn + b0g) * Dn], Dn,
                        &g_Wp[j * 64],
                        &g_XWraw[(size_t)(t * Bn + b0g) * NP + j * 64],
                        Dn, sh_gemm);
        }
        barrier_sync(g, GCTA, epL);

        // ---------------- LN of xW rows -> spre; init carries ----------------
        for (int lr = c; lr < Tn * GB; lr += GCTA) {
            int t = lr >> 6, bl = lr & 63;
            const float* row = &g_XWraw[(size_t)(t * Bn + b0g + bl) * NP];
            float v0 = row[tid];
            float v1 = row[tid + 256];
            float v2 = (tid == 0) ? row[512] : 0.f;
            float s = v0 + v1 + v2;
            float q = v0 * v0 + v1 * v1 + v2 * v2;
#pragma unroll
            for (int o = 16; o > 0; o >>= 1) {
                s += __shfl_down_sync(0xffffffffu, s, o);
                q += __shfl_down_sync(0xffffffffu, q, o);
            }
            if ((tid & 31) == 0) { sh_red[tid >> 5] = s; sh_red[8 + (tid >> 5)] = q; }
            __syncthreads();
            if (tid == 0) {
                float S = 0.f, Q = 0.f;
#pragma unroll
                for (int w = 0; w < 8; w++) { S += sh_red[w]; Q += sh_red[8 + w]; }
                float mean = S * (1.f / (float)Nn);
                float var  = Q * (1.f / (float)Nn) - mean * mean;
                sh_sc[0] = mean;
                sh_sc[1] = 1.f / (sqrtf(var + EPSV) + EPSV);
            }
            __syncthreads();
            float mean = sh_sc[0], inv = sh_sc[1];
            float* o = &g_spre[(size_t)(t * Bn + b0g + bl) * NP];
            o[tid]       = gam0[tid] * ((v0 - mean) * inv) + bet0[tid] + bias[tid];
            o[tid + 256] = gam0[tid + 256] * ((v1 - mean) * inv) + bet0[tid + 256] + bias[tid + 256];
            if (tid == 0)
                o[512] = gam0[512] * ((v2 - mean) * inv) + bet0[512] + bias[512];
            __syncthreads();
        }
        for (int i = c * NTHR + tid; i < GB * Dn; i += GCTA * NTHR)
            g_h[(size_t)b0g * Dn + i] = 0.f;
        for (int i = c * NTHR + tid; i < GB; i += GCTA * NTHR) {
            g_fk[b0g + i] = 0.f;
            g_hv[b0g + i] = 0.f;
        }
        barrier_sync(g, GCTA, epL);

        // ------------------------------ scan ---------------------------------
        for (int t = 0; t < Tn; t++) {
            // phase A: split-K h@U partials (144 of 148 CTAs, K-chunk = 64)
            if (c < 9 * KS) {
                int ks = c / 9, j = c - ks * 9;
                tile_gemm64(&g_h[(size_t)b0g * Dn + ks * 64], Dn,
                            &g_Up[(size_t)(ks * 64) * NP + j * 64],
                            &g_Gpart[(size_t)((g * KS + ks) * GB) * NP + j * 64],
                            64, sh_gemm);
            }
            barrier_sync(g, GCTA, epL);

            // phase B: one CTA per batch
            if (c < GB) {
                int b = b0g + c;
                float v0 = 0.f, v1 = 0.f, v2 = 0.f;
#pragma unroll
                for (int ks = 0; ks < KS; ks++) {
                    const float* gp = &g_Gpart[(size_t)((g * KS + ks) * GB + c) * NP];
                    v0 += gp[tid];
                    v1 += gp[tid + 256];
                    if (tid == 0) v2 += gp[512];
                }
                float s = v0 + v1 + v2;
                float q = v0 * v0 + v1 * v1 + v2 * v2;
#pragma unroll
                for (int o = 16; o > 0; o >>= 1) {
                    s += __shfl_down_sync(0xffffffffu, s, o);
                    q += __shfl_down_sync(0xffffffffu, q, o);
                }
                if ((tid & 31) == 0) { sh_red[tid >> 5] = s; sh_red[8 + (tid >> 5)] = q; }
                __syncthreads();
                if (tid == 0) {
                    float S = 0.f, Q = 0.f;
#pragma unroll
                    for (int w = 0; w < 8; w++) { S += sh_red[w]; Q += sh_red[8 + w]; }
                    float mean = S * (1.f / (float)Nn);
                    float var  = Q * (1.f / (float)Nn) - mean * mean;
                    sh_sc[0] = mean;
                    sh_sc[1] = 1.f / (sqrtf(var + EPSV) + EPSV);
                }
                __syncthreads();
                float mean = sh_sc[0], inv = sh_sc[1];

                const float* sp = &g_spre[(size_t)(t * Bn + b) * NP];
                float sum2_0 = gam1[0] * ((v0 - mean) * inv) + bet1[0]; // tid 0 only
                float s0 = sp[tid]       + gam1[tid]       * ((v0 - mean) * inv) + bet1[tid];
                float s1 = sp[tid + 256] + gam1[tid + 256] * ((v1 - mean) * inv) + bet1[tid + 256];
                sh_s[tid]       = s0;
                sh_s[tid + 256] = s1;
                if (tid == 0)
                    sh_s[512] = sp[512] + gam1[512] * ((v2 - mean) * inv) + bet1[512];

                if (tid == 0) {
                    float fk_tm1  = g_fk[b];
                    float hv_tm1  = g_hv[b];
                    float fkp_tm1 = g_fkseq[t * Bn + b];
                    float fkp     = (t + 1 < Tn) ? g_fkseq[(t + 1) * Bn + b] : 0.f;
                    float hvp     = g_hvseq[t * Bn + b];
                    bool  mk      = mask[b * Tn + t] > 0;
                    bool  mkprev  = (t > 0) ? (mask[b * Tn + t - 1] > 0) : false;
                    bool  mk2     = (t > 0) && mkprev && !mk;

                    float fk_both = fminf(fmaxf(0.2f * s0 + 0.5f, 0.f), 1.f);
                    float fk_t1   = fminf(fmaxf(0.2f * (sum2_0 + bias[0]) + 0.5f, 0.f), 1.f);
                    float fk = fkp_tm1 + (1.f - fkp_tm1) *
                               (fk_tm1 * fk_both + (1.f - fk_tm1) * fk_t1);
                    if (mk2) fk = 0.f;

                    float h_only = hv_tm1 * fk * (fkp + (1.f - fkp) * (1.f - hvp));
                    float x_only = hvp * (1.f - fkp) * (1.f - fk + fk * (1.f - hv_tm1));
                    float both   = (1.f - fkp) * fk * hv_tm1 * hvp;
                    float hv = 1.f - (1.f - h_only) * (1.f - x_only) * (1.f - both);

                    float fk_out = mk ? fk : fk_tm1;
                    float hv_out = mk ? hv : hv_tm1;
                    if (mk2) fk_out = 0.f;

                    sh_sc[2] = h_only; sh_sc[3] = x_only;
                    sh_sc[4] = both;   sh_sc[5] = mk ? 1.f : 0.f;

                    g_fk[b] = fk_out;
                    g_hv[b] = hv_out;
                    g_fkseq[t * Bn + b] = fk_out;
                    g_hvseq[t * Bn + b] = hv_out;
                }
                __syncthreads();

                float h_only = sh_sc[2], x_only = sh_sc[3];
                float both = sh_sc[4], mkf = sh_sc[5];
#pragma unroll
                for (int e = 0; e < 4; e++) {
                    int d = tid + (e << 8);
                    float x_t   = g_X[(size_t)(t * Bn + b) * Dn + d];
                    float h_tm1 = g_h[(size_t)b * Dn + d];
                    float h_new = (d < In) ? 0.f : tanhf(sh_s[d - (In - 1)]);
                    float h = h_only * h_tm1 + x_only * x_t + both * h_new;
                    h = mkf * h + (1.f - mkf) * h_tm1;
                    g_h[(size_t)b * Dn + d] = h;
                    g_X[(size_t)(t * Bn + b) * Dn + d] = h;
                }
            }
            barrier_sync(g, GCTA, epL);
        }
    }

    // ------------------------------ output ----------------------------------
    for (int i = c * NTHR + tid; i < GB * Hn; i += GCTA * NTHR) {
        int bl = i >> 9, j = i & 511;
        out[(size_t)(b0g + bl) * Hn + j] = g_h[(size_t)(b0g + bl) * Dn + In + j];
    }
}

// ------------------------------- launcher -----------------------------------
extern "C" void kernel_launch(void* const* d_in, const int* in_sizes, int n_in,
                              void* d_out, int out_size) {
    const float* x      = (const float*)d_in[0];
    const int*   mask   = (const int*)d_in[1];
    const float* W      = (const float*)d_in[2];
    const float* U      = (const float*)d_in[3];
    const float* bias   = (const float*)d_in[4];
    const float* gammas = (const float*)d_in[5];
    const float* betas  = (const float*)d_in[6];
    float* out = (float*)d_out;

    hrnn_kernel<<<NCTA, NTHR>>>(x, mask, W, U, bias, gammas, betas, out);
}